// round 11
// baseline (speedup 1.0000x reference)
#include <cuda_runtime.h>
#include <cuda_fp16.h>
#include <cstdint>

#define NN 8192
#define DD 64
#define EK 262144
#define EHK 262144
#define ETOT (EHK + EK)
#define TAB 2048

#define MB2 296                // phase2 matvec blocks
#define EB2 592                // phase2 edge blocks
#define EW2 (EB2 * 8)
#define M2SPLIT 5504           // matvec rows done in phase2

#define GEMMB 64               // GEMM blocks: 64 x (M=128 rows)
#define MB3 160                // phase3 matvec blocks

#define SSTRIDE 144            // padded smem row pitch (bytes) for 128B rows
#define SA_BUF (128 * SSTRIDE) // 18432 B per A buffer
#define SB_BUF (64 * SSTRIDE)  // 9216 B per B buffer
#define SMEM3 (2 * SA_BUF + 2 * SB_BUF)   // 55296 B

// ---- scratch (device globals; allocation-free) ----
__device__ float  g_sk[NN * DD];       // normalized state_K (fp32)
__device__ __half g_skH[NN * DD];      // normalized state_K (fp16, row-major)
__device__ float  g_g[NN];             // tanh(state_H)
__device__ float  g_fK[NN * DD];       // GEMM output (edge sums)
__device__ float  g_fHa[NN];           // f_H edge accumulator
__device__ float  g_tab[TAB + 1];      // dE(s) table
__device__ __half g_A[(size_t)NN * NN];// 8192x8192 fp16 coef matrix (128MB).
                                       // Zero at module load; restored each launch by fin.

__device__ __forceinline__ uint32_t smem_u32(const void* p) {
    uint32_t a;
    asm("{ .reg .u64 t; cvta.to.shared.u64 t, %1; cvt.u32.u64 %0, t; }" : "=r"(a) : "l"(p));
    return a;
}
__device__ __forceinline__ void red1(float* p, float a) {
    asm volatile("red.global.add.f32 [%0], %1;" :: "l"(p), "f"(a));
}
__device__ __forceinline__ void redh(size_t idx, float coef) {
    unsigned short h = __half_as_ushort(__float2half(coef));
    uint32_t v = (idx & 1) ? ((uint32_t)h << 16) : (uint32_t)h;
    char* p = (char*)g_A + (idx & ~(size_t)1) * 2;
    asm volatile("red.global.add.noftz.f16x2 [%0], %1;" :: "l"(p), "r"(v));
}
__device__ __forceinline__ float warp_sum(float v) {
    #pragma unroll
    for (int o = 16; o; o >>= 1) v += __shfl_xor_sync(0xFFFFFFFFu, v, o);
    return v;
}

#define CP_ASYNC(d, s) asm volatile("cp.async.cg.shared.global [%0], [%1], 16;" :: "r"(d), "l"(s))
#define CP_COMMIT()    asm volatile("cp.async.commit_group;" ::: "memory")
#define CP_WAIT1()     asm volatile("cp.async.wait_group 1;" ::: "memory")
#define CP_WAIT0()     asm volatile("cp.async.wait_group 0;" ::: "memory")
#define LDSM4(r0, r1, r2, r3, a) \
    asm volatile("ldmatrix.sync.aligned.m8n8.x4.shared.b16 {%0,%1,%2,%3}, [%4];" \
        : "=r"(r0), "=r"(r1), "=r"(r2), "=r"(r3) : "r"(a))
#define LDSM4T(r0, r1, r2, r3, a) \
    asm volatile("ldmatrix.sync.aligned.m8n8.x4.trans.shared.b16 {%0,%1,%2,%3}, [%4];" \
        : "=r"(r0), "=r"(r1), "=r"(r2), "=r"(r3) : "r"(a))
#define MMA(cp, a0, a1, a2, a3, b0, b1) \
    asm volatile("mma.sync.aligned.m16n8k16.row.col.f32.f16.f16.f32 " \
        "{%0,%1,%2,%3}, {%4,%5,%6,%7}, {%8,%9}, {%0,%1,%2,%3};" \
        : "+f"((cp)[0]), "+f"((cp)[1]), "+f"((cp)[2]), "+f"((cp)[3]) \
        : "r"(a0), "r"(a1), "r"(a2), "r"(a3), "r"(b0), "r"(b1))

// --- prep: normalize sk (fp32 + fp16 copies), g=tanh(sH), zero fHa, build table.
__global__ void prep_kernel(const float* __restrict__ sH, const float* __restrict__ sK,
                            const float* __restrict__ w1, const float* __restrict__ b1,
                            const float* __restrict__ w2) {
    int warp = threadIdx.x >> 5, lane = threadIdx.x & 31;
    int row = blockIdx.x * 8 + warp;
    float2 v = ((const float2*)(sK + row * DD))[lane];
    float ss = warp_sum(v.x * v.x + v.y * v.y);
    float inv = rsqrtf(ss);
    float nx = v.x * inv, ny = v.y * inv;
    ((float2*)(g_sk + row * DD))[lane] = make_float2(nx, ny);
    ((__half2*)(g_skH + row * DD))[lane] = __floats2half2_rn(nx, ny);
    if (lane == 0) g_g[row] = tanhf(sH[row]);

    int gt = blockIdx.x * 256 + threadIdx.x;
    if (gt < NN / 4) ((float4*)g_fHa)[gt] = make_float4(0.f, 0.f, 0.f, 0.f);

    int entry = blockIdx.x * 8 + warp;                // warp-per-table-entry
    if (entry <= TAB) {
        float s = entry * (2.0f / TAB) - 1.0f;
        float a0 = tanhf(s * __ldg(w1 + lane)      + __ldg(b1 + lane))      * __ldg(w2 + lane);
        float a1 = tanhf(s * __ldg(w1 + lane + 32) + __ldg(b1 + lane + 32)) * __ldg(w2 + lane + 32);
        float acc = warp_sum(a0 + a1);
        if (lane == 0) g_tab[entry] = acc;
    }
}

// matvec body: f_H[row] = -sH[row] + W_H[row,:] @ g
__device__ __forceinline__ void matvec_rows(int beg, int end, int idx, int stride,
                                            const float* __restrict__ sH,
                                            const float* __restrict__ W,
                                            float* __restrict__ out) {
    __shared__ float rr[8];
    int lane = threadIdx.x & 31, warp = threadIdx.x >> 5;
    const float4* g4 = (const float4*)g_g;
    for (int row = beg + idx; row < end; row += stride) {
        const float4* Wr = (const float4*)(W + (size_t)row * NN);
        float acc = 0.f;
        #pragma unroll
        for (int it = 0; it < 8; it++) {
            int k = threadIdx.x + it * 256;
            float4 w = __ldcs(Wr + k);
            float4 g = g4[k];
            acc += w.x * g.x + w.y * g.y + w.z * g.z + w.w * g.w;
        }
        acc = warp_sum(acc);
        if (lane == 0) rr[warp] = acc;
        __syncthreads();
        if (threadIdx.x == 0) {
            float v = rr[0] + rr[1] + rr[2] + rr[3] + rr[4] + rr[5] + rr[6] + rr[7];
            out[row] = -sH[row] + v;
        }
        __syncthreads();
    }
}

// --- phase2: edges (dot -> coef -> A[i][j],A[j][i] fp16 red) + matvec rows [0,M2SPLIT).
__global__ __launch_bounds__(256, 6) void phase2_kernel(
    const float* __restrict__ sH, const float* __restrict__ W,
    const int* __restrict__ indK, const int* __restrict__ indHK,
    float* __restrict__ out)
{
    int lane = threadIdx.x & 31, warp = threadIdx.x >> 5;
    if (blockIdx.x < MB2) { matvec_rows(0, M2SPLIT, blockIdx.x, MB2, sH, W, out); return; }

    int c = lane & 15;
    int wg = (blockIdx.x - MB2) * 8 + warp;
    #pragma unroll 2
    for (int e = wg; e < ETOT; e += EW2) {
        bool isHK = e < EHK;
        int2 ij = isHK ? __ldg((const int2*)indHK + e)
                       : __ldg((const int2*)indK + (e - EHK));
        int myRow = (lane < 16) ? ij.x : ij.y;
        float4 v = __ldg((const float4*)(g_sk + myRow * DD) + c);
        float4 w;
        w.x = __shfl_xor_sync(0xFFFFFFFFu, v.x, 16);
        w.y = __shfl_xor_sync(0xFFFFFFFFu, v.y, 16);
        w.z = __shfl_xor_sync(0xFFFFFFFFu, v.z, 16);
        w.w = __shfl_xor_sync(0xFFFFFFFFu, v.w, 16);
        float d = v.x * w.x + v.y * w.y + v.z * w.z + v.w * w.w;
        d += __shfl_xor_sync(0xFFFFFFFFu, d, 1);
        d += __shfl_xor_sync(0xFFFFFFFFu, d, 2);
        d += __shfl_xor_sync(0xFFFFFFFFu, d, 4);
        d += __shfl_xor_sync(0xFFFFFFFFu, d, 8);   // s = <row_i, row_j>
        float coef;
        if (isHK) {
            float gm = __ldg(g_g + myRow);
            float gp = __shfl_xor_sync(0xFFFFFFFFu, gm, 16);
            if ((lane & 15) == 0)
                red1(g_fHa + myRow, d * gp * 0.5f);     // /KAPPA_H
            coef = -0.5f * gm * gp;                     // -G/KAPPA_K
        } else {
            float t = (fminf(fmaxf(d, -1.f), 1.f) + 1.f) * (TAB * 0.5f);
            int i0 = min((int)t, TAB - 1);
            float f = t - (float)i0;
            float t0 = __ldg(g_tab + i0), t1 = __ldg(g_tab + i0 + 1);
            coef = t0 + (t1 - t0) * f;                  // dE(s)
        }
        if ((lane & 15) == 0) {
            int partner = (lane < 16) ? ij.y : ij.x;
            redh((size_t)myRow * NN + partner, coef);   // A[myRow][partner] += coef
        }
    }
}

// --- phase3: f_K edge sums = A @ skH via mma.sync GEMM + matvec rows [M2SPLIT, NN).
__global__ __launch_bounds__(256) void phase3_kernel(
    const float* __restrict__ sH, const float* __restrict__ W, float* __restrict__ out)
{
    if (blockIdx.x >= GEMMB) {
        matvec_rows(M2SPLIT, NN, blockIdx.x - GEMMB, MB3, sH, W, out);
        return;
    }
    extern __shared__ char dsm[];
    uint32_t sb = smem_u32(dsm);
    uint32_t sA[2] = { sb, sb + SA_BUF };
    uint32_t sB[2] = { sb + 2 * SA_BUF, sb + 2 * SA_BUF + SB_BUF };

    int tid = threadIdx.x, wid = tid >> 5, lane = tid & 31;
    int mb = blockIdx.x;                  // m-tile: rows [mb*128, mb*128+128)
    int rowA = tid >> 1, halfseg = tid & 1;

    const char* gA = (const char*)(g_A + (size_t)(mb * 128 + rowA) * NN);
    const char* gB = (const char*)g_skH;

    // prologue: prefetch chunk 0
    {
        uint32_t dA = sA[0] + rowA * SSTRIDE + halfseg * 64;
        const char* srcA = gA + halfseg * 64;
        #pragma unroll
        for (int u = 0; u < 4; u++) CP_ASYNC(dA + u * 16, srcA + u * 16);
        if (tid < 128) {
            uint32_t dB = sB[0] + rowA * SSTRIDE + halfseg * 64;
            const char* srcB = gB + (size_t)rowA * 128 + halfseg * 64;
            #pragma unroll
            for (int u = 0; u < 4; u++) CP_ASYNC(dB + u * 16, srcB + u * 16);
        }
        CP_COMMIT();
    }

    float acc[32];
    #pragma unroll
    for (int i = 0; i < 32; i++) acc[i] = 0.f;

    int rsel = lane & 15;
    int csel = (lane >> 4) * 16;          // bytes: column +8 halves for upper lanes

    for (int ch = 0; ch < 128; ch++) {
        if (ch + 1 < 128) {
            int buf = (ch + 1) & 1;
            int kc = (ch + 1) * 64;       // halves
            uint32_t dA = sA[buf] + rowA * SSTRIDE + halfseg * 64;
            const char* srcA = gA + kc * 2 + halfseg * 64;
            #pragma unroll
            for (int u = 0; u < 4; u++) CP_ASYNC(dA + u * 16, srcA + u * 16);
            if (tid < 128) {
                uint32_t dB = sB[buf] + rowA * SSTRIDE + halfseg * 64;
                const char* srcB = gB + (size_t)(kc + rowA) * 128 + halfseg * 64;
                #pragma unroll
                for (int u = 0; u < 4; u++) CP_ASYNC(dB + u * 16, srcB + u * 16);
            }
            CP_COMMIT();
            CP_WAIT1();
        } else {
            CP_WAIT0();
        }
        __syncthreads();

        int buf = ch & 1;
        uint32_t a_base = sA[buf] + (wid * 16 + rsel) * SSTRIDE + csel;
        uint32_t b_rowbase = sB[buf] + rsel * SSTRIDE + csel;
        #pragma unroll
        for (int ks = 0; ks < 4; ks++) {
            uint32_t a0, a1, a2, a3;
            LDSM4(a0, a1, a2, a3, a_base + ks * 32);
            #pragma unroll
            for (int nt2 = 0; nt2 < 4; nt2++) {
                uint32_t b0, b1, b2, b3;
                LDSM4T(b0, b1, b2, b3, b_rowbase + ks * 16 * SSTRIDE + nt2 * 32);
                MMA(acc + 8 * nt2,     a0, a1, a2, a3, b0, b1);
                MMA(acc + 8 * nt2 + 4, a0, a1, a2, a3, b2, b3);
            }
        }
        __syncthreads();
    }

    // write result tiles: warp rows mb*128 + wid*16 + {g, g+8}
    int g = lane >> 2, tg = lane & 3;
    int r0 = mb * 128 + wid * 16 + g;
    #pragma unroll
    for (int nt = 0; nt < 8; nt++) {
        int col = nt * 8 + 2 * tg;
        *(float2*)(g_fK + (size_t)r0 * DD + col)       = make_float2(acc[4 * nt],     acc[4 * nt + 1]);
        *(float2*)(g_fK + (size_t)(r0 + 8) * DD + col) = make_float2(acc[4 * nt + 2], acc[4 * nt + 3]);
    }
}

// --- phase4: finalize + restore A to zeros at touched entries.
__global__ void fin_kernel(const float* __restrict__ omega,
                           const int* __restrict__ indK, const int* __restrict__ indHK,
                           float* __restrict__ out) {
    if (blockIdx.x >= NN / 8) {
        int e = (blockIdx.x - NN / 8) * 256 + threadIdx.x;   // 0..ETOT-1
        int2 ij = (e < EHK) ? __ldg((const int2*)indHK + e)
                            : __ldg((const int2*)indK + (e - EHK));
        g_A[(size_t)ij.x * NN + ij.y] = __ushort_as_half((unsigned short)0);
        g_A[(size_t)ij.y * NN + ij.x] = __ushort_as_half((unsigned short)0);
        return;
    }
    __shared__ float A[DD * DD];
    __shared__ float srow[8 * DD];
    for (int k = threadIdx.x; k < DD * DD; k += 256) {
        int rI = k >> 6, cc = k & 63;
        A[k] = 0.5f * (omega[k] - omega[cc * DD + rI]);
    }
    __syncthreads();
    int warp = threadIdx.x >> 5, lane = threadIdx.x & 31;
    int row = blockIdx.x * 8 + warp;
    if (lane == 0) out[row] += g_fHa[row];
    float2 skv = ((const float2*)(g_sk + row * DD))[lane];
    float2 fv  = ((const float2*)(g_fK + row * DD))[lane];
    float d = warp_sum(skv.x * fv.x + skv.y * fv.y);
    ((float2*)(srow + warp * DD))[lane] = skv;
    __syncwarp();
    const float* sr = srow + warp * DD;
    const float2* A2 = (const float2*)A;
    float m0 = 0.f, m1 = 0.f;
    #pragma unroll
    for (int k = 0; k < DD; k++) {
        float sv = sr[k];
        float2 av = A2[k * 32 + lane];
        m0 += sv * av.x;
        m1 += sv * av.y;
    }
    float o0 = -fv.x + skv.x * d + m0;
    float o1 = -fv.y + skv.y * d + m1;
    ((float2*)(out + NN + row * DD))[lane] = make_float2(o0, o1);
}

extern "C" void kernel_launch(void* const* d_in, const int* in_sizes, int n_in,
                              void* d_out, int out_size) {
    const float* sH   = (const float*)d_in[0];
    const float* sK   = (const float*)d_in[1];
    const float* WH   = (const float*)d_in[2];
    const float* om   = (const float*)d_in[3];
    const float* w1   = (const float*)d_in[4];
    const float* b1   = (const float*)d_in[5];
    const float* w2   = (const float*)d_in[6];
    const int*  indK  = (const int*)d_in[7];
    const int*  indHK = (const int*)d_in[8];
    float* out = (float*)d_out;

    cudaFuncSetAttribute(phase3_kernel, cudaFuncAttributeMaxDynamicSharedMemorySize, SMEM3);

    prep_kernel<<<NN / 8, 256>>>(sH, sK, w1, b1, w2);
    phase2_kernel<<<MB2 + EB2, 256>>>(sH, WH, indK, indHK, out);
    phase3_kernel<<<GEMMB + MB3, 256, SMEM3>>>(sH, WH, out);
    fin_kernel<<<NN / 8 + ETOT / 256, 256>>>(om, indK, indHK, out);
}

// round 12
// speedup vs baseline: 2.2039x; 2.2039x over previous
#include <cuda_runtime.h>
#include <cstdint>

#define NN 8192
#define DD 64
#define EK 262144
#define EHK 262144
#define ETOT (EHK + EK)
#define TAB 2048
#define NB 888                 // total blocks = 6/SM x 148 SMs (all co-resident)
#define MB 296                 // matvec worker blocks (2 per SM)
#define EB 592                 // edge worker blocks (4 per SM)
#define EWARPS (EB * 8)        // 4736 edge warps
#define GW (NB * 8)            // 7104 grid warps
#define GT (NB * 256)          // 227328 grid threads

// Scratch (device globals: allocation-free)
__device__ float g_sk[NN * DD];   // normalized state_K
__device__ float g_g[NN];         // tanh(state_H)
__device__ float g_fK[NN * DD];   // f_K edge accumulator
__device__ float g_fHa[NN];       // f_H edge accumulator
__device__ float g_tab[TAB + 1];  // dE(s) lookup table, s in [-1,1]
__device__ unsigned g_tick;       // ticket barrier counter (monotonic across launches)

// No "memory" clobber: g_fK/g_fHa are write-only in part B.
__device__ __forceinline__ void red4(float* p, float a, float b, float c, float d) {
    asm volatile("red.global.add.v4.f32 [%0], {%1,%2,%3,%4};"
                 :: "l"(p), "f"(a), "f"(b), "f"(c), "f"(d));
}
__device__ __forceinline__ void red1(float* p, float a) {
    asm volatile("red.global.add.f32 [%0], %1;" :: "l"(p), "f"(a));
}
__device__ __forceinline__ float warp_sum(float v) {
    #pragma unroll
    for (int o = 16; o; o >>= 1) v += __shfl_xor_sync(0xFFFFFFFFu, v, o);
    return v;
}

// Grid-wide ticket barrier. Counter never resets: each barrier consumes NB
// increments; target = next multiple of NB. Safe across graph replays.
// Requires all NB blocks co-resident (exact-fit occupancy).
__device__ __forceinline__ void grid_bar() {
    __syncthreads();
    if (threadIdx.x == 0) {
        __threadfence();
        unsigned v = atomicAdd(&g_tick, 1u);
        unsigned target = (v / NB) * NB + NB;
        unsigned cur;
        for (;;) {
            asm volatile("ld.global.acquire.gpu.u32 %0, [%1];" : "=r"(cur) : "l"(&g_tick));
            if (cur >= target) break;
            asm volatile("nanosleep.u32 64;");
        }
    }
    __syncthreads();
}

__global__ __launch_bounds__(256, 6) void fused_kernel(
    const float* __restrict__ sH, const float* __restrict__ sK,
    const float* __restrict__ W, const float* __restrict__ omega,
    const float* __restrict__ w1, const float* __restrict__ b1,
    const float* __restrict__ w2,
    const int* __restrict__ indK, const int* __restrict__ indHK,
    float* __restrict__ out)
{
    __shared__ float rr[8];
    __shared__ float shA[DD * DD];    // antisymmetrized omega (part C)
    __shared__ float srow[8 * DD];

    int lane = threadIdx.x & 31, warp = threadIdx.x >> 5;
    int gw = blockIdx.x * 8 + warp;          // 0..7103
    int gt = blockIdx.x * 256 + threadIdx.x; // 0..227327

    // ================= Part A: prep =================
    for (int row = gw; row < NN; row += GW) {
        float2 v = ((const float2*)(sK + row * DD))[lane];
        float ss = warp_sum(v.x * v.x + v.y * v.y);
        float inv = rsqrtf(ss);
        ((float2*)(g_sk + row * DD))[lane] = make_float2(v.x * inv, v.y * inv);
        if (lane == 0) g_g[row] = tanhf(sH[row]);
    }
    for (int entry = gw; entry <= TAB; entry += GW) {
        float s = entry * (2.0f / TAB) - 1.0f;
        float a0 = tanhf(s * __ldg(w1 + lane)      + __ldg(b1 + lane))      * __ldg(w2 + lane);
        float a1 = tanhf(s * __ldg(w1 + lane + 32) + __ldg(b1 + lane + 32)) * __ldg(w2 + lane + 32);
        float acc = warp_sum(a0 + a1);
        if (lane == 0) g_tab[entry] = acc;
    }
    for (int i = gt; i < NN * DD / 4; i += GT)
        ((float4*)g_fK)[i] = make_float4(0.f, 0.f, 0.f, 0.f);
    if (gt < NN / 4)
        ((float4*)g_fHa)[gt] = make_float4(0.f, 0.f, 0.f, 0.f);

    grid_bar();

    // ================= Part B: matvec + edges =================
    if (blockIdx.x < MB) {
        // ---- matvec worker: rows blockIdx.x, +MB, ... keeps DRAM saturated.
        const float4* g4 = (const float4*)g_g;
        for (int row = blockIdx.x; row < NN; row += MB) {
            const float4* Wr = (const float4*)(W + (size_t)row * NN);
            float acc = 0.f;
            #pragma unroll
            for (int it = 0; it < 8; it++) {
                int k = threadIdx.x + it * 256;
                float4 w = __ldcs(Wr + k);     // stream: don't pollute L2
                float4 g = g4[k];
                acc += w.x * g.x + w.y * g.y + w.z * g.z + w.w * g.w;
            }
            acc = warp_sum(acc);
            if (lane == 0) rr[warp] = acc;
            __syncthreads();
            if (threadIdx.x == 0) {
                float v = rr[0] + rr[1] + rr[2] + rr[3] + rr[4] + rr[5] + rr[6] + rr[7];
                out[row] = -sH[row] + v;
            }
            __syncthreads();
        }
    } else {
        // ---- edge worker: warp-per-edge, half-warp per endpoint.
        int c = lane & 15;                    // float4 chunk within row
        int wg = (blockIdx.x - MB) * 8 + warp;
        #pragma unroll 2
        for (int e = wg; e < ETOT; e += EWARPS) {
            bool isHK = e < EHK;
            int2 ij = isHK ? __ldg((const int2*)indHK + e)
                           : __ldg((const int2*)indK + (e - EHK));
            int myRow = (lane < 16) ? ij.x : ij.y;
            float4 v = __ldg((const float4*)(g_sk + myRow * DD) + c);
            float4 w;                          // partner row chunk
            w.x = __shfl_xor_sync(0xFFFFFFFFu, v.x, 16);
            w.y = __shfl_xor_sync(0xFFFFFFFFu, v.y, 16);
            w.z = __shfl_xor_sync(0xFFFFFFFFu, v.z, 16);
            w.w = __shfl_xor_sync(0xFFFFFFFFu, v.w, 16);
            float d = v.x * w.x + v.y * w.y + v.z * w.z + v.w * w.w;
            d += __shfl_xor_sync(0xFFFFFFFFu, d, 1);
            d += __shfl_xor_sync(0xFFFFFFFFu, d, 2);
            d += __shfl_xor_sync(0xFFFFFFFFu, d, 4);
            d += __shfl_xor_sync(0xFFFFFFFFu, d, 8);   // s = <row_i, row_j>
            float coef;
            if (isHK) {
                float gm = __ldg(g_g + myRow);
                float gp = __shfl_xor_sync(0xFFFFFFFFu, gm, 16);
                if ((lane & 15) == 0)                       // lanes 0 and 16
                    red1(g_fHa + myRow, d * gp * 0.5f);     // /KAPPA_H
                coef = -0.5f * gm * gp;                     // -G/KAPPA_K
            } else {
                float t = (fminf(fmaxf(d, -1.f), 1.f) + 1.f) * (TAB * 0.5f);
                int i0 = min((int)t, TAB - 1);
                float f = t - (float)i0;
                float t0 = __ldg(g_tab + i0), t1 = __ldg(g_tab + i0 + 1);
                coef = t0 + (t1 - t0) * f;                  // dE(s)
            }
            red4(g_fK + myRow * DD + c * 4, coef * w.x, coef * w.y, coef * w.z, coef * w.w);
        }
    }

    grid_bar();

    // ================= Part C: finalize =================
    for (int k = threadIdx.x; k < DD * DD; k += 256) {
        int rI = k >> 6, cc = k & 63;
        shA[k] = 0.5f * (omega[k] - omega[cc * DD + rI]);
    }
    __syncthreads();
    const float2* A2 = (const float2*)shA;
    for (int grp = blockIdx.x; grp < NN / 8; grp += NB) {
        int row = grp * 8 + warp;
        if (lane == 0) out[row] += g_fHa[row];            // finish f_H
        float2 skv = ((const float2*)(g_sk + row * DD))[lane];
        float2 fv  = ((const float2*)(g_fK + row * DD))[lane];
        float d = warp_sum(skv.x * fv.x + skv.y * fv.y);
        ((float2*)(srow + warp * DD))[lane] = skv;
        __syncwarp();
        const float* sr = srow + warp * DD;
        float m0 = 0.f, m1 = 0.f;
        #pragma unroll
        for (int k = 0; k < DD; k++) {
            float sv = sr[k];
            float2 av = A2[k * 32 + lane];
            m0 += sv * av.x;
            m1 += sv * av.y;
        }
        float o0 = -fv.x + skv.x * d + m0;
        float o1 = -fv.y + skv.y * d + m1;
        ((float2*)(out + NN + row * DD))[lane] = make_float2(o0, o1);
        __syncwarp();
    }
}

extern "C" void kernel_launch(void* const* d_in, const int* in_sizes, int n_in,
                              void* d_out, int out_size) {
    const float* sH   = (const float*)d_in[0];
    const float* sK   = (const float*)d_in[1];
    const float* WH   = (const float*)d_in[2];
    const float* om   = (const float*)d_in[3];
    const float* w1   = (const float*)d_in[4];
    const float* b1   = (const float*)d_in[5];
    const float* w2   = (const float*)d_in[6];
    const int*  indK  = (const int*)d_in[7];
    const int*  indHK = (const int*)d_in[8];
    float* out = (float*)d_out;

    fused_kernel<<<NB, 256>>>(sH, sK, WH, om, w1, b1, w2, indK, indHK, out);
}

// round 13
// speedup vs baseline: 2.4516x; 1.1124x over previous
#include <cuda_runtime.h>
#include <cuda_fp16.h>
#include <cstdint>

#define NN 8192
#define DD 64
#define EK 262144
#define EHK 262144
#define ETOT (EHK + EK)
#define TAB 2048
#define MB 296                 // matvec worker blocks (2 per SM)
#define EB 592                 // edge worker blocks (4 per SM)
#define EWARPS (EB * 8)        // 4736 edge warps

// Scratch (device globals: allocation-free)
__device__ float  g_sk[NN * DD];    // normalized state_K (fp32, for fin)
__device__ __half g_skh[NN * DD];   // normalized state_K (fp16, for edge phase)
__device__ float  g_g[NN];          // tanh(state_H)
__device__ float  g_fK[NN * DD];    // f_K edge accumulator (fp32, exact)
__device__ float  g_fHa[NN];        // f_H edge accumulator
__device__ float2 g_tab2[TAB + 1];  // dE table: (f(s_i), f(s_{i+1}))

// No "memory" clobber: g_fK/g_fHa are write-only in mega.
__device__ __forceinline__ void red4(float* p, float a, float b, float c, float d) {
    asm volatile("red.global.add.v4.f32 [%0], {%1,%2,%3,%4};"
                 :: "l"(p), "f"(a), "f"(b), "f"(c), "f"(d));
}
__device__ __forceinline__ void red1(float* p, float a) {
    asm volatile("red.global.add.f32 [%0], %1;" :: "l"(p), "f"(a));
}
__device__ __forceinline__ float warp_sum(float v) {
    #pragma unroll
    for (int o = 16; o; o >>= 1) v += __shfl_xor_sync(0xFFFFFFFFu, v, o);
    return v;
}

// --- prep: normalize sk (fp32 + fp16 mirror), g=tanh(sH), zero accum, table.
__global__ void prep_kernel(const float* __restrict__ sH, const float* __restrict__ sK,
                            const float* __restrict__ w1, const float* __restrict__ b1,
                            const float* __restrict__ w2) {
    int warp = threadIdx.x >> 5, lane = threadIdx.x & 31;
    int row = blockIdx.x * 8 + warp;
    float2 v = ((const float2*)(sK + row * DD))[lane];
    float ss = warp_sum(v.x * v.x + v.y * v.y);
    float inv = rsqrtf(ss);
    float nx = v.x * inv, ny = v.y * inv;
    ((float2*)(g_sk + row * DD))[lane] = make_float2(nx, ny);
    ((__half2*)(g_skh + row * DD))[lane] = __floats2half2_rn(nx, ny);
    if (lane == 0) g_g[row] = tanhf(sH[row]);

    int gt = blockIdx.x * 256 + threadIdx.x;          // 0..262143
    if (gt < NN * DD / 4) ((float4*)g_fK)[gt] = make_float4(0.f, 0.f, 0.f, 0.f);
    if (gt < NN / 4)      ((float4*)g_fHa)[gt] = make_float4(0.f, 0.f, 0.f, 0.f);

    int entry = blockIdx.x * 8 + warp;                // warp-per-table-entry
    if (entry <= TAB) {
        float s0 = entry * (2.0f / TAB) - 1.0f;
        float s1 = s0 + (2.0f / TAB);
        float wa = __ldg(w1 + lane),      ba = __ldg(b1 + lane),      ca = __ldg(w2 + lane);
        float wb = __ldg(w1 + lane + 32), bb = __ldg(b1 + lane + 32), cb = __ldg(w2 + lane + 32);
        float fa = warp_sum(tanhf(s0 * wa + ba) * ca + tanhf(s0 * wb + bb) * cb);
        float fb = warp_sum(tanhf(s1 * wa + ba) * ca + tanhf(s1 * wb + bb) * cb);
        if (lane == 0) g_tab2[entry] = make_float2(fa, fb);
    }
}

// --- mega: persistent workers. Blocks 0..MB-1: matvec rows (grid-stride).
//     Blocks MB..MB+EB-1: edges (warp grid-stride over EHK+EK jobs).
__global__ __launch_bounds__(256, 6) void mega_kernel(
    const float* __restrict__ sH, const float* __restrict__ W,
    const int* __restrict__ indK, const int* __restrict__ indHK,
    float* __restrict__ out)
{
    int lane = threadIdx.x & 31, warp = threadIdx.x >> 5;

    if (blockIdx.x < MB) {
        // ---- matvec worker: rows blockIdx.x, +MB, ... keeps DRAM saturated.
        __shared__ float rr[8];
        const float4* g4 = (const float4*)g_g;
        for (int row = blockIdx.x; row < NN; row += MB) {
            const float4* Wr = (const float4*)(W + (size_t)row * NN);
            float acc = 0.f;
            #pragma unroll
            for (int it = 0; it < 8; it++) {
                int k = threadIdx.x + it * 256;
                float4 w = __ldcs(Wr + k);     // stream: don't pollute L2
                float4 g = g4[k];
                acc += w.x * g.x + w.y * g.y + w.z * g.z + w.w * g.w;
            }
            acc = warp_sum(acc);
            if (lane == 0) rr[warp] = acc;
            __syncthreads();
            if (threadIdx.x == 0) {
                float v = rr[0] + rr[1] + rr[2] + rr[3] + rr[4] + rr[5] + rr[6] + rr[7];
                out[row] = -sH[row] + v;
            }
            __syncthreads();
        }
        return;
    }

    // ---- edge worker: warp-per-edge, half-warp per endpoint, fp16 gather.
    int c = lane & 15;                    // 8-byte chunk (4 halves) within fp16 row
    int wg = (blockIdx.x - MB) * 8 + warp;
    #pragma unroll 2
    for (int e = wg; e < ETOT; e += EWARPS) {
        bool isHK = e < EHK;
        int2 ij = isHK ? __ldg((const int2*)indHK + e)
                       : __ldg((const int2*)indK + (e - EHK));
        int myRow = (lane < 16) ? ij.x : ij.y;
        uint2 vh = __ldg((const uint2*)(g_skh + myRow * DD) + c);  // 4 halves of my row
        uint2 wh;                          // partner row chunk
        wh.x = __shfl_xor_sync(0xFFFFFFFFu, vh.x, 16);
        wh.y = __shfl_xor_sync(0xFFFFFFFFu, vh.y, 16);
        float2 va = __half22float2(*(const __half2*)&vh.x);
        float2 vb = __half22float2(*(const __half2*)&vh.y);
        float2 wa = __half22float2(*(const __half2*)&wh.x);
        float2 wb = __half22float2(*(const __half2*)&wh.y);
        float d = va.x * wa.x + va.y * wa.y + vb.x * wb.x + vb.y * wb.y;
        d += __shfl_xor_sync(0xFFFFFFFFu, d, 1);
        d += __shfl_xor_sync(0xFFFFFFFFu, d, 2);
        d += __shfl_xor_sync(0xFFFFFFFFu, d, 4);
        d += __shfl_xor_sync(0xFFFFFFFFu, d, 8);   // s = <row_i, row_j>
        float coef;
        if (isHK) {
            float gm = __ldg(g_g + myRow);
            float gp = __shfl_xor_sync(0xFFFFFFFFu, gm, 16);
            if ((lane & 15) == 0)                       // lanes 0 and 16
                red1(g_fHa + myRow, d * gp * 0.5f);     // /KAPPA_H
            coef = -0.5f * gm * gp;                     // -G/KAPPA_K
        } else {
            float t = (fminf(fmaxf(d, -1.f), 1.f) + 1.f) * (TAB * 0.5f);
            int i0 = min((int)t, TAB - 1);
            float f = t - (float)i0;
            float2 tt = __ldg(g_tab2 + i0);
            coef = tt.x + (tt.y - tt.x) * f;            // dE(s)
        }
        // endpoint myRow accumulates coef * partner_row chunk (4 floats), fp32 red
        red4(g_fK + myRow * DD + c * 4,
             coef * wa.x, coef * wa.y, coef * wb.x, coef * wb.y);
    }
}

// --- finalize: f_H += fHacc; f_K = -acc + sk*<sk,acc> + sk @ (omega-omega^T)/2.
__global__ void fin_kernel(const float* __restrict__ omega, float* __restrict__ out) {
    __shared__ float A[DD * DD];      // antisymmetrized omega
    __shared__ float srow[8 * DD];
    for (int k = threadIdx.x; k < DD * DD; k += 256) {
        int rI = k >> 6, cc = k & 63;
        A[k] = 0.5f * (omega[k] - omega[cc * DD + rI]);
    }
    __syncthreads();
    int warp = threadIdx.x >> 5, lane = threadIdx.x & 31;
    int row = blockIdx.x * 8 + warp;
    if (lane == 0) out[row] += g_fHa[row];            // finish f_H
    float2 skv = ((const float2*)(g_sk + row * DD))[lane];
    float2 fv  = ((const float2*)(g_fK + row * DD))[lane];
    float d = warp_sum(skv.x * fv.x + skv.y * fv.y);
    ((float2*)(srow + warp * DD))[lane] = skv;
    __syncwarp();
    const float* sr = srow + warp * DD;
    const float2* A2 = (const float2*)A;
    float m0 = 0.f, m1 = 0.f;
    #pragma unroll
    for (int k = 0; k < DD; k++) {
        float sv = sr[k];
        float2 av = A2[k * 32 + lane];
        m0 += sv * av.x;
        m1 += sv * av.y;
    }
    float o0 = -fv.x + skv.x * d + m0;
    float o1 = -fv.y + skv.y * d + m1;
    ((float2*)(out + NN + row * DD))[lane] = make_float2(o0, o1);
}

extern "C" void kernel_launch(void* const* d_in, const int* in_sizes, int n_in,
                              void* d_out, int out_size) {
    const float* sH   = (const float*)d_in[0];
    const float* sK   = (const float*)d_in[1];
    const float* WH   = (const float*)d_in[2];
    const float* om   = (const float*)d_in[3];
    const float* w1   = (const float*)d_in[4];
    const float* b1   = (const float*)d_in[5];
    const float* w2   = (const float*)d_in[6];
    const int*  indK  = (const int*)d_in[7];
    const int*  indHK = (const int*)d_in[8];
    float* out = (float*)d_out;

    prep_kernel<<<NN / 8, 256>>>(sH, sK, w1, b1, w2);
    mega_kernel<<<MB + EB, 256>>>(sH, WH, indK, indHK, out);
    fin_kernel<<<NN / 8, 256>>>(om, out);
}